// round 10
// baseline (speedup 1.0000x reference)
#include <cuda_runtime.h>

#define BB    32
#define CINC  32
#define COUTC 32
#define TT    2048
#define DKK   32
#define NFFT  4096
#define FH    2064   // half-spectrum row stride (f = 0..2048 valid; 16-float2 aligned)

// FFT dynamic smem: 4096-pt buffer + 1024-entry twiddle table
#define FFT_SMEM_BYTES ((NFFT + 1024) * sizeof(float2))   // 40960

// smem bank-conflict swizzle for the FFT buffer (float2 index domain)
#define SW(i) ((i) ^ ((((i) >> 4) & 15)))

// ---- scratch (device globals; allocation-free) -----------------------------
__device__ float  g_buf[COUTC * CINC * TT];   // [o*32+i][d]   8 MB
__device__ float2 Xf[1024 * FH];              // [b*32+i][f]
__device__ float2 Gf[1024 * FH];              // [o*32+i][f]
__device__ float2 Of[1024 * FH];              // [b*32+o][f]

__device__ __forceinline__ float2 cmulf(float2 a, float2 b) {
    return make_float2(a.x * b.x - a.y * b.y, a.x * b.y + a.y * b.x);
}
__device__ __forceinline__ float2 caddf(float2 a, float2 b) { return make_float2(a.x + b.x, a.y + b.y); }
__device__ __forceinline__ float2 csubf(float2 a, float2 b) { return make_float2(a.x - b.x, a.y - b.y); }

// packed f32x2 helpers (Blackwell FFMA2)
typedef unsigned long long ull;
__device__ __forceinline__ ull pk2(float lo, float hi) {
    ull d; asm("mov.b64 %0, {%1, %2};" : "=l"(d) : "f"(lo), "f"(hi)); return d;
}
__device__ __forceinline__ void upk2(float& lo, float& hi, ull v) {
    asm("mov.b64 {%0, %1}, %2;" : "=f"(lo), "=f"(hi) : "l"(v));
}
__device__ __forceinline__ ull fma2(ull a, ull b, ull c) {
    ull d; asm("fma.rn.f32x2 %0, %1, %2, %3;" : "=l"(d) : "l"(a), "l"(b), "l"(c)); return d;
}

// twiddle fetch: W = exp(-2pi*i*e/4096) (fwd) or conj (inv), from 1024-entry table
template<bool INV>
__device__ __forceinline__ float2 twget(const float2* tws, int e) {
    int idx = e & 1023;
    int q   = (e >> 10) & 3;
    float2 w = tws[idx];
    if (INV) w.y = -w.y;
    if (q & 1) w = INV ? make_float2(-w.y, w.x) : make_float2(w.y, -w.x);
    if (q & 2) w = make_float2(-w.x, -w.y);
    return w;
}

// ---------------------------------------------------------------------------
// 16-point DFT codelet (registers only, in place).
// ---------------------------------------------------------------------------
template<bool INV>
__device__ __forceinline__ void dft16(float2* a) {
    const float c1 = 0.92387953251128675613f;
    const float s1 = 0.38268343236508977173f;
    const float Cc = 0.70710678118654752440f;
    float2 B[16];
#pragma unroll
    for (int n0 = 0; n0 < 4; n0++) {
        float2 p0 = a[n0], p1 = a[4 + n0], p2 = a[8 + n0], p3 = a[12 + n0];
        float2 t0 = caddf(p0, p2), t1 = csubf(p0, p2);
        float2 t2 = caddf(p1, p3), t3 = csubf(p1, p3);
        float2 t3r = INV ? make_float2(-t3.y, t3.x) : make_float2(t3.y, -t3.x);
        B[n0 * 4 + 0] = caddf(t0, t2);
        B[n0 * 4 + 1] = caddf(t1, t3r);
        B[n0 * 4 + 2] = csubf(t0, t2);
        B[n0 * 4 + 3] = csubf(t1, t3r);
    }
    const float sg = INV ? 1.f : -1.f;
    const float2 w1 = make_float2(c1, sg * s1);
    const float2 w2 = make_float2(Cc, sg * Cc);
    const float2 w3 = make_float2(s1, sg * c1);
    const float2 w6 = make_float2(-Cc, sg * Cc);
    const float2 w9 = make_float2(-c1, -sg * s1);
    B[5]  = cmulf(B[5],  w1);
    B[6]  = cmulf(B[6],  w2);
    B[7]  = cmulf(B[7],  w3);
    B[9]  = cmulf(B[9],  w2);
    B[10] = INV ? make_float2(-B[10].y, B[10].x) : make_float2(B[10].y, -B[10].x);
    B[11] = cmulf(B[11], w6);
    B[13] = cmulf(B[13], w3);
    B[14] = cmulf(B[14], w6);
    B[15] = cmulf(B[15], w9);
#pragma unroll
    for (int r0 = 0; r0 < 4; r0++) {
        float2 p0 = B[r0], p1 = B[4 + r0], p2 = B[8 + r0], p3 = B[12 + r0];
        float2 t0 = caddf(p0, p2), t1 = csubf(p0, p2);
        float2 t2 = caddf(p1, p3), t3 = csubf(p1, p3);
        float2 t3r = INV ? make_float2(-t3.y, t3.x) : make_float2(t3.y, -t3.x);
        a[r0]      = caddf(t0, t2);
        a[4 + r0]  = caddf(t1, t3r);
        a[8 + r0]  = csubf(t0, t2);
        a[12 + r0] = csubf(t1, t3r);
    }
}

// ---------------------------------------------------------------------------
// SIREN MLP -> g_buf.  g[o,i,d] = kern[o,i,2048-d], d in [0,2048).
// ---------------------------------------------------------------------------
__global__ void __launch_bounds__(256)
gen_kernel(const float* __restrict__ rel_pos,
           const float* __restrict__ w1,
           const float* __restrict__ b1,
           const float* __restrict__ omega1p,
           const float* __restrict__ w2,
           const float* __restrict__ b2,
           const float* __restrict__ omega2p,
           const float* __restrict__ w3,
           const float* __restrict__ b3) {
    __shared__ float h2s[128][33];
    __shared__ float w3s[128][32];
    __shared__ float b3s[128];
    const int tid = threadIdx.x;
    const int j2b0 = blockIdx.y * 128;

#pragma unroll
    for (int q = 0; q < 4; q++) {
        int flat4 = tid + 256 * q;
        int row = flat4 >> 3;
        int c4  = flat4 & 7;
        ((float4*)&w3s[row][0])[c4] = ((const float4*)(w3 + (size_t)(j2b0 + row) * 32))[c4];
    }
    if (tid < 128) b3s[tid] = b3[j2b0 + tid];

    if (tid < 128) {
        const int kl = tid;
        const int k  = 1 + blockIdx.x * 128 + kl;
        const float pos = rel_pos[k];
        const float o1 = *omega1p, o2 = *omega2p;
        float h1[DKK];
#pragma unroll
        for (int j = 0; j < DKK; j++)
            h1[j] = sinf(o1 * (w1[j] * pos + b1[j]));
        for (int j = 0; j < DKK; j++) {
            float a = b2[j];
#pragma unroll
            for (int l = 0; l < DKK; l++)
                a += w2[j * DKK + l] * h1[l];
            h2s[kl][j] = sinf(o2 * a);
        }
    }
    __syncthreads();

    const int kl   = tid & 127;
    const int half = tid >> 7;
    const int k    = 1 + blockIdx.x * 128 + kl;
    const int d    = 2048 - k;
    float h2r[32];
#pragma unroll
    for (int l = 0; l < 32; l++) h2r[l] = h2s[kl][l];

    for (int jj = 0; jj < 64; jj++) {
        const int row = half * 64 + jj;
        float a = b3s[row];
#pragma unroll
        for (int l4 = 0; l4 < 8; l4++) {
            float4 w = ((const float4*)&w3s[row][0])[l4];
            a += w.x * h2r[4*l4+0] + w.y * h2r[4*l4+1]
               + w.z * h2r[4*l4+2] + w.w * h2r[4*l4+3];
        }
        g_buf[(size_t)(j2b0 + row) * TT + d] = a;
    }
}

// ---------------------------------------------------------------------------
// 4096-pt radix-16 Stockham FFT (3 stages), packed-real, one pair per block.
// 256 threads x 16 elements. All twiddles via independent table lookups
// (1024-entry quarter table) -- no serial power chains.
// FWD: blockIdx.x<512 -> x rows -> Xf ; >=512 -> g rows -> Gf
// INV: full spectrum of O1 + i*O2 rebuilt in the register load; out = re/im.
// ---------------------------------------------------------------------------
template<bool INV>
__global__ void __launch_bounds__(256, 4)
fft4096_kernel(const float* __restrict__ rsrc,
               float* __restrict__ rdst,
               const float* __restrict__ bias) {
    extern __shared__ float2 dyn[];
    float2* buf = dyn;                 // NFFT (swizzled indexing)
    float2* tws = dyn + NFFT;          // 1024
    const int tid = threadIdx.x;

    const int sig = INV ? blockIdx.x : (blockIdx.x & 511);   // pair index
    const int isG = INV ? 0 : (blockIdx.x >> 9);
    const int hb  = sig >> 4;
    const int ip  = sig & 15;
    const int rowA = hb * 32 + 2 * ip;

    // twiddle table exp(-2pi*i*t/4096), t < 1024
#pragma unroll
    for (int q = 0; q < 4; q++) {
        int t = tid + 256 * q;
        float s, c;
        sincospif(-(float)t / 2048.0f, &s, &c);
        tws[t] = make_float2(c, s);
    }

    // ---- stage 0: registers straight from global --------------------------
    float2 a[16];
    if (!INV) {
        const float* baseA = isG ? (g_buf + (size_t)rowA * TT)
                                 : (rsrc + (size_t)rowA * TT);
        const float* baseB = baseA + TT;
#pragma unroll
        for (int r = 0; r < 8; r++) {
            int idx = tid + 256 * r;
            a[r] = make_float2(baseA[idx], baseB[idx]);
        }
#pragma unroll
        for (int r = 8; r < 16; r++) a[r] = make_float2(0.f, 0.f);   // folded
    } else {
        const float2* srcA = Of + (size_t)rowA * FH;
        const float2* srcB = srcA + FH;
#pragma unroll
        for (int r = 0; r < 16; r++) {
            int f = tid + 256 * r;
            if (f <= 2048) {
                float2 o1 = srcA[f], o2 = srcB[f];
                a[r] = make_float2(o1.x - o2.y, o1.y + o2.x);
            } else {
                int fp = NFFT - f;               // 1..2047, reversed-coalesced
                float2 o1 = srcA[fp], o2 = srcB[fp];
                a[r] = make_float2(o1.x + o2.y, o2.x - o1.y);
            }
        }
    }
    __syncthreads();       // table visible to all before stage-0 lookups
    dft16<INV>(a);
    {   // jm = tid, k = 0, m = 1
        const int wb = 16 * tid;
        buf[SW(wb)] = a[0];
#pragma unroll
        for (int r = 1; r < 16; r++)
            buf[SW(wb + r)] = cmulf(a[r], twget<INV>(tws, tid * r));
    }
    __syncthreads();

    // ---- stage 1: smem -> smem (m = 16) ------------------------------------
    {
#pragma unroll
        for (int r = 0; r < 16; r++) a[r] = buf[SW(tid + 256 * r)];
        __syncthreads();
        dft16<INV>(a);
        const int k  = tid & 15;
        const int jm = tid - k;
        const int wb = 16 * jm + k;
        buf[SW(wb)] = a[0];
#pragma unroll
        for (int r = 1; r < 16; r++)
            buf[SW(wb + 16 * r)] = cmulf(a[r], twget<INV>(tws, jm * r));
        __syncthreads();
    }

    // ---- stage 2: smem -> registers (m = 256; jm = 0, no twiddles) --------
#pragma unroll
    for (int r = 0; r < 16; r++) a[r] = buf[SW(tid + 256 * r)];
    dft16<INV>(a);
    // output index of a[r] is exactly tid + 256*r

    if (!INV) {
        __syncthreads();
#pragma unroll
        for (int r = 0; r < 16; r++) buf[SW(tid + 256 * r)] = a[r];
        __syncthreads();
        float2* dstA = (isG ? Gf : Xf) + (size_t)rowA * FH;
        float2* dstB = dstA + FH;
#pragma unroll
        for (int q = 0; q < 8; q++) {
            int f  = tid + 256 * q;              // 0..2047
            int fm = (NFFT - f) & (NFFT - 1);
            float2 z  = buf[SW(f)];
            float2 zm = buf[SW(fm)];
            dstA[f] = make_float2(0.5f * (z.x + zm.x), 0.5f * (z.y - zm.y));
            dstB[f] = make_float2(0.5f * (z.y + zm.y), 0.5f * (zm.x - z.x));
        }
        if (tid == 0) {
            float2 z = buf[SW(2048)];
            dstA[2048] = make_float2(z.x, 0.f);
            dstB[2048] = make_float2(z.y, 0.f);
        }
    } else {
        const float sc = 1.0f / (float)NFFT;
        const float bv1 = bias[(rowA) & 31];
        const float bv2 = bias[(rowA + 1) & 31];
        float* dst1 = rdst + (size_t)rowA * TT;
        float* dst2 = dst1 + TT;
#pragma unroll
        for (int r = 0; r < 8; r++) {
            int t = tid + 256 * r;
            dst1[t] = a[r].x * sc + bv1;
            dst2[t] = a[r].y * sc + bv2;
        }
    }
}

// ---------------------------------------------------------------------------
// Pointwise per-frequency complex GEMM, pre-splatted FFMA2 form:
//   Of[b,o,f] = sum_i Xf[b,i,f] * Gf[o,i,f]
// grid (129, 2) = (f-tile 16, o-half 16), 512 threads, 32 b per block.
// Xs2[(ii,b,ff)]  = { (x.re,x.re), (x.im,x.im) }   (ulonglong2)
// Gs2[(ii,oo,ff)] = { (g.re,g.im), (-g.im,g.re) }  (ulonglong2)
// Thread (ff, oog, bbg): acc[2][8] packed complex accumulators (32 regs).
// ---------------------------------------------------------------------------
__global__ void __launch_bounds__(512)
pointwise_kernel() {
    __shared__ ulonglong2 Xs2[4 * 32 * 16];   // 32 KB
    __shared__ ulonglong2 Gs2[4 * 16 * 16];   // 16 KB
    const int tid = threadIdx.x;
    const int f0  = blockIdx.x * 16;
    const int o0  = blockIdx.y * 16;
    const int ff  = tid & 15;
    const int oog = (tid >> 4) & 7;           // o = o0 + oog*2 + j
    const int bbg = tid >> 7;                 // b = bbg*8 + l

    ull acc[2][8];
#pragma unroll
    for (int j = 0; j < 2; j++)
#pragma unroll
        for (int l = 0; l < 8; l++) acc[j][l] = 0ull;

    for (int ic = 0; ic < 32; ic += 4) {
        __syncthreads();
        // stage X: 2048 elements = 1024 float4 reads
#pragma unroll
        for (int q = 0; q < 2; q++) {
            int flat2 = tid + 512 * q;        // = ii*256 + rr*8 + f2
            int f2 = flat2 & 7;
            int rr = (flat2 >> 3) & 31;
            int ii = flat2 >> 8;
            int row = rr * 32 + ic + ii;
            float4 v = ((const float4*)(Xf + (size_t)row * FH + f0))[f2];
            int e = ii * 512 + rr * 16 + 2 * f2;
            Xs2[e]     = make_ulonglong2(pk2(v.x, v.x), pk2(v.y, v.y));
            Xs2[e + 1] = make_ulonglong2(pk2(v.z, v.z), pk2(v.w, v.w));
        }
        // stage G: 1024 elements = 512 float4 reads
        {
            int f2 = tid & 7;
            int rr = (tid >> 3) & 15;
            int ii = tid >> 7;
            int row = (o0 + rr) * 32 + ic + ii;
            float4 v = ((const float4*)(Gf + (size_t)row * FH + f0))[f2];
            int e = ii * 256 + rr * 16 + 2 * f2;
            Gs2[e]     = make_ulonglong2(pk2(v.x, v.y), pk2(-v.y, v.x));
            Gs2[e + 1] = make_ulonglong2(pk2(v.z, v.w), pk2(-v.w, v.z));
        }
        __syncthreads();
#pragma unroll
        for (int ii = 0; ii < 4; ii++) {
            ulonglong2 g0 = Gs2[ii * 256 + (oog * 2 + 0) * 16 + ff];
            ulonglong2 g1 = Gs2[ii * 256 + (oog * 2 + 1) * 16 + ff];
#pragma unroll
            for (int l = 0; l < 8; l++) {
                ulonglong2 xs = Xs2[ii * 512 + (bbg * 8 + l) * 16 + ff];
                acc[0][l] = fma2(xs.x, g0.x, acc[0][l]);
                acc[0][l] = fma2(xs.y, g0.y, acc[0][l]);
                acc[1][l] = fma2(xs.x, g1.x, acc[1][l]);
                acc[1][l] = fma2(xs.y, g1.y, acc[1][l]);
            }
        }
    }
#pragma unroll
    for (int j = 0; j < 2; j++)
#pragma unroll
        for (int l = 0; l < 8; l++) {
            float2 v;
            upk2(v.x, v.y, acc[j][l]);
            int b = bbg * 8 + l;
            int o = o0 + oog * 2 + j;
            Of[(size_t)(b * 32 + o) * FH + f0 + ff] = v;
        }
}

// ---------------------------------------------------------------------------
extern "C" void kernel_launch(void* const* d_in, const int* in_sizes, int n_in,
                              void* d_out, int out_size) {
    const float* x       = (const float*)d_in[0];
    const float* rel_pos = (const float*)d_in[1];
    const float* w1      = (const float*)d_in[2];
    const float* b1      = (const float*)d_in[3];
    const float* omega1  = (const float*)d_in[4];
    const float* w2      = (const float*)d_in[5];
    const float* b2      = (const float*)d_in[6];
    const float* omega2  = (const float*)d_in[7];
    const float* w3      = (const float*)d_in[8];
    const float* b3      = (const float*)d_in[9];
    const float* bias    = (const float*)d_in[10];
    float* out = (float*)d_out;

    gen_kernel<<<dim3(16, 8), 256>>>(rel_pos, w1, b1, omega1, w2, b2, omega2, w3, b3);
    fft4096_kernel<false><<<1024, 256, FFT_SMEM_BYTES>>>(x, nullptr, nullptr);  // x->Xf, g->Gf
    pointwise_kernel<<<dim3(129, 2), 512>>>();                                  // Xf*Gf -> Of
    fft4096_kernel<true><<<512, 256, FFT_SMEM_BYTES>>>(nullptr, out, bias);     // Of -> out
}

// round 11
// speedup vs baseline: 1.2287x; 1.2287x over previous
#include <cuda_runtime.h>

#define BB    32
#define CINC  32
#define COUTC 32
#define TT    2048
#define DKK   32
#define NFFT  4096
#define FH    2064   // half-spectrum row stride (f = 0..2048 valid; 16-float2 aligned)

// FFT dynamic smem: 4096-pt buffer + 256-entry twiddle table
#define FFT_SMEM_BYTES ((NFFT + 256) * sizeof(float2))   // 34816

// smem bank-conflict swizzle for the FFT buffer (float2 index domain)
#define SW(i) ((i) ^ ((((i) >> 4) & 15)))

// ---- scratch (device globals; allocation-free) -----------------------------
__device__ float  g_buf[COUTC * CINC * TT];   // [o*32+i][d]   8 MB
__device__ float2 Xf[1024 * FH];              // [b*32+i][f]
__device__ float2 Gf[1024 * FH];              // [o*32+i][f]
__device__ float2 Of[1024 * FH];              // [b*32+o][f]

__device__ __forceinline__ float2 cmulf(float2 a, float2 b) {
    return make_float2(a.x * b.x - a.y * b.y, a.x * b.y + a.y * b.x);
}
__device__ __forceinline__ float2 caddf(float2 a, float2 b) { return make_float2(a.x + b.x, a.y + b.y); }
__device__ __forceinline__ float2 csubf(float2 a, float2 b) { return make_float2(a.x - b.x, a.y - b.y); }

// packed f32x2 helpers (Blackwell FFMA2)
typedef unsigned long long ull;
__device__ __forceinline__ ull pk2(float lo, float hi) {
    ull d; asm("mov.b64 %0, {%1, %2};" : "=l"(d) : "f"(lo), "f"(hi)); return d;
}
__device__ __forceinline__ void upk2(float& lo, float& hi, ull v) {
    asm("mov.b64 {%0, %1}, %2;" : "=f"(lo), "=f"(hi) : "l"(v));
}
__device__ __forceinline__ ull fma2(ull a, ull b, ull c) {
    ull d; asm("fma.rn.f32x2 %0, %1, %2, %3;" : "=l"(d) : "l"(a), "l"(b), "l"(c)); return d;
}

// ---------------------------------------------------------------------------
// 16-point DFT codelet (registers only, in place).
// ---------------------------------------------------------------------------
template<bool INV>
__device__ __forceinline__ void dft16(float2* a) {
    const float c1 = 0.92387953251128675613f;
    const float s1 = 0.38268343236508977173f;
    const float Cc = 0.70710678118654752440f;
    float2 B[16];
#pragma unroll
    for (int n0 = 0; n0 < 4; n0++) {
        float2 p0 = a[n0], p1 = a[4 + n0], p2 = a[8 + n0], p3 = a[12 + n0];
        float2 t0 = caddf(p0, p2), t1 = csubf(p0, p2);
        float2 t2 = caddf(p1, p3), t3 = csubf(p1, p3);
        float2 t3r = INV ? make_float2(-t3.y, t3.x) : make_float2(t3.y, -t3.x);
        B[n0 * 4 + 0] = caddf(t0, t2);
        B[n0 * 4 + 1] = caddf(t1, t3r);
        B[n0 * 4 + 2] = csubf(t0, t2);
        B[n0 * 4 + 3] = csubf(t1, t3r);
    }
    const float sg = INV ? 1.f : -1.f;
    const float2 w1 = make_float2(c1, sg * s1);
    const float2 w2 = make_float2(Cc, sg * Cc);
    const float2 w3 = make_float2(s1, sg * c1);
    const float2 w6 = make_float2(-Cc, sg * Cc);
    const float2 w9 = make_float2(-c1, -sg * s1);
    B[5]  = cmulf(B[5],  w1);
    B[6]  = cmulf(B[6],  w2);
    B[7]  = cmulf(B[7],  w3);
    B[9]  = cmulf(B[9],  w2);
    B[10] = INV ? make_float2(-B[10].y, B[10].x) : make_float2(B[10].y, -B[10].x);
    B[11] = cmulf(B[11], w6);
    B[13] = cmulf(B[13], w3);
    B[14] = cmulf(B[14], w6);
    B[15] = cmulf(B[15], w9);
#pragma unroll
    for (int r0 = 0; r0 < 4; r0++) {
        float2 p0 = B[r0], p1 = B[4 + r0], p2 = B[8 + r0], p3 = B[12 + r0];
        float2 t0 = caddf(p0, p2), t1 = csubf(p0, p2);
        float2 t2 = caddf(p1, p3), t3 = csubf(p1, p3);
        float2 t3r = INV ? make_float2(-t3.y, t3.x) : make_float2(t3.y, -t3.x);
        a[r0]      = caddf(t0, t2);
        a[4 + r0]  = caddf(t1, t3r);
        a[8 + r0]  = csubf(t0, t2);
        a[12 + r0] = csubf(t1, t3r);
    }
}

// ---------------------------------------------------------------------------
// SIREN MLP -> g_buf.  g[o,i,d] = kern[o,i,2048-d], d in [0,2048).
// ---------------------------------------------------------------------------
__global__ void __launch_bounds__(256)
gen_kernel(const float* __restrict__ rel_pos,
           const float* __restrict__ w1,
           const float* __restrict__ b1,
           const float* __restrict__ omega1p,
           const float* __restrict__ w2,
           const float* __restrict__ b2,
           const float* __restrict__ omega2p,
           const float* __restrict__ w3,
           const float* __restrict__ b3) {
    __shared__ float h2s[128][33];
    __shared__ float w3s[128][32];
    __shared__ float b3s[128];
    const int tid = threadIdx.x;
    const int j2b0 = blockIdx.y * 128;

#pragma unroll
    for (int q = 0; q < 4; q++) {
        int flat4 = tid + 256 * q;
        int row = flat4 >> 3;
        int c4  = flat4 & 7;
        ((float4*)&w3s[row][0])[c4] = ((const float4*)(w3 + (size_t)(j2b0 + row) * 32))[c4];
    }
    if (tid < 128) b3s[tid] = b3[j2b0 + tid];

    if (tid < 128) {
        const int kl = tid;
        const int k  = 1 + blockIdx.x * 128 + kl;
        const float pos = rel_pos[k];
        const float o1 = *omega1p, o2 = *omega2p;
        float h1[DKK];
#pragma unroll
        for (int j = 0; j < DKK; j++)
            h1[j] = sinf(o1 * (w1[j] * pos + b1[j]));
        for (int j = 0; j < DKK; j++) {
            float a = b2[j];
#pragma unroll
            for (int l = 0; l < DKK; l++)
                a += w2[j * DKK + l] * h1[l];
            h2s[kl][j] = sinf(o2 * a);
        }
    }
    __syncthreads();

    const int kl   = tid & 127;
    const int half = tid >> 7;
    const int k    = 1 + blockIdx.x * 128 + kl;
    const int d    = 2048 - k;
    float h2r[32];
#pragma unroll
    for (int l = 0; l < 32; l++) h2r[l] = h2s[kl][l];

    for (int jj = 0; jj < 64; jj++) {
        const int row = half * 64 + jj;
        float a = b3s[row];
#pragma unroll
        for (int l4 = 0; l4 < 8; l4++) {
            float4 w = ((const float4*)&w3s[row][0])[l4];
            a += w.x * h2r[4*l4+0] + w.y * h2r[4*l4+1]
               + w.z * h2r[4*l4+2] + w.w * h2r[4*l4+3];
        }
        g_buf[(size_t)(j2b0 + row) * TT + d] = a;
    }
}

// ---------------------------------------------------------------------------
// 4096-pt radix-16 Stockham FFT (3 stages), packed-real, one pair per block.
// 256 threads, 16 elements each (R8 version: chained twiddles, direct
// global loads in stage 0, direct stores for the inverse).
// FWD: blockIdx.x<512 -> x rows -> Xf ; >=512 -> g rows -> Gf
// INV: full spectrum of O1 + i*O2 rebuilt in the register load; out = re/im.
// ---------------------------------------------------------------------------
template<bool INV>
__global__ void __launch_bounds__(256, 4)
fft4096_kernel(const float* __restrict__ rsrc,
               float* __restrict__ rdst,
               const float* __restrict__ bias) {
    extern __shared__ float2 dyn[];
    float2* buf = dyn;                 // NFFT (swizzled indexing)
    float2* tws = dyn + NFFT;          // 256
    const int tid = threadIdx.x;

    const int sig = INV ? blockIdx.x : (blockIdx.x & 511);   // pair index
    const int isG = INV ? 0 : (blockIdx.x >> 9);
    const int hb  = sig >> 4;
    const int ip  = sig & 15;
    const int rowA = hb * 32 + 2 * ip;

    // twiddle table exp(-2πi t/4096); own entry also used as stage-0 twiddle
    float sv, cv;
    sincospif(-(float)tid / 2048.0f, &sv, &cv);
    tws[tid] = make_float2(cv, sv);

    // ---- stage 0: registers straight from global --------------------------
    float2 a[16];
    if (!INV) {
        const float* baseA = isG ? (g_buf + (size_t)rowA * TT)
                                 : (rsrc + (size_t)rowA * TT);
        const float* baseB = baseA + TT;
#pragma unroll
        for (int r = 0; r < 8; r++) {
            int idx = tid + 256 * r;
            a[r] = make_float2(baseA[idx], baseB[idx]);
        }
#pragma unroll
        for (int r = 8; r < 16; r++) a[r] = make_float2(0.f, 0.f);   // folded
    } else {
        const float2* srcA = Of + (size_t)rowA * FH;
        const float2* srcB = srcA + FH;
#pragma unroll
        for (int r = 0; r < 16; r++) {
            int f = tid + 256 * r;
            if (f <= 2048) {
                float2 o1 = srcA[f], o2 = srcB[f];
                a[r] = make_float2(o1.x - o2.y, o1.y + o2.x);
            } else {
                int fp = NFFT - f;               // 1..2047, reversed-coalesced
                float2 o1 = srcA[fp], o2 = srcB[fp];
                a[r] = make_float2(o1.x + o2.y, o2.x - o1.y);
            }
        }
    }
    dft16<INV>(a);
    {   // jm = tid, k = 0, m = 1 -> own twiddle, no table dependency
        float2 W1 = make_float2(cv, INV ? -sv : sv);
        const int wb = 16 * tid;
        buf[SW(wb)] = a[0];
        float2 Wc = W1;
#pragma unroll
        for (int r = 1; r < 16; r++) {
            buf[SW(wb + r)] = cmulf(a[r], Wc);
            Wc = cmulf(Wc, W1);
        }
    }
    __syncthreads();

    // ---- stage 1: smem -> smem (m = 16) ------------------------------------
    {
#pragma unroll
        for (int r = 0; r < 16; r++) a[r] = buf[SW(tid + 256 * r)];
        __syncthreads();
        dft16<INV>(a);
        const int k  = tid & 15;
        const int jm = tid - k;
        const int wb = 16 * jm + k;
        float2 W1 = tws[jm];
        if (INV) W1.y = -W1.y;
        buf[SW(wb)] = a[0];
        float2 Wc = W1;
#pragma unroll
        for (int r = 1; r < 16; r++) {
            buf[SW(wb + 16 * r)] = cmulf(a[r], Wc);
            Wc = cmulf(Wc, W1);
        }
        __syncthreads();
    }

    // ---- stage 2: smem -> registers (m = 256; jm = 0, no twiddles) --------
#pragma unroll
    for (int r = 0; r < 16; r++) a[r] = buf[SW(tid + 256 * r)];
    dft16<INV>(a);
    // output index of a[r] is exactly tid + 256*r

    if (!INV) {
        // need cross-thread mirror for unpack: one smem round
        __syncthreads();
#pragma unroll
        for (int r = 0; r < 16; r++) buf[SW(tid + 256 * r)] = a[r];
        __syncthreads();
        float2* dstA = (isG ? Gf : Xf) + (size_t)rowA * FH;
        float2* dstB = dstA + FH;
#pragma unroll
        for (int q = 0; q < 8; q++) {
            int f  = tid + 256 * q;              // 0..2047
            int fm = (NFFT - f) & (NFFT - 1);
            float2 z  = buf[SW(f)];
            float2 zm = buf[SW(fm)];
            dstA[f] = make_float2(0.5f * (z.x + zm.x), 0.5f * (z.y - zm.y));
            dstB[f] = make_float2(0.5f * (z.y + zm.y), 0.5f * (zm.x - z.x));
        }
        if (tid == 0) {
            float2 z = buf[SW(2048)];
            dstA[2048] = make_float2(z.x, 0.f);
            dstB[2048] = make_float2(z.y, 0.f);
        }
    } else {
        // direct register -> global store
        const float sc = 1.0f / (float)NFFT;
        const float bv1 = bias[(rowA) & 31];
        const float bv2 = bias[(rowA + 1) & 31];
        float* dst1 = rdst + (size_t)rowA * TT;
        float* dst2 = dst1 + TT;
#pragma unroll
        for (int r = 0; r < 8; r++) {
            int t = tid + 256 * r;
            dst1[t] = a[r].x * sc + bv1;
            dst2[t] = a[r].y * sc + bv2;
        }
    }
}

// ---------------------------------------------------------------------------
// Pointwise per-frequency complex GEMM (FFMA2, 2-blocks/SM tiling):
//   Of[b,o,f] = sum_i Xf[b,i,f] * Gf[o,i,f]
// grid (129, 2) = (f-tile 16, o-half 16), 512 threads, all 32 b per block.
// Thread (ff, oog, bbg): acc[2][8] packed accumulators (32 regs; <=64 total
// via launch_bounds minBlocks=2 so TWO blocks fit per SM).
// Staging keeps the R8 conflict-free float2 layout.
// ---------------------------------------------------------------------------
__global__ void __launch_bounds__(512, 2)
pointwise_kernel() {
    __shared__ float2 Xs[4 * 32 * 16];   // [ii][b][ff] 16 KB
    __shared__ float2 Gs[4 * 16 * 16];   // [ii][oo][ff] 8 KB
    const int tid = threadIdx.x;
    const int f0  = blockIdx.x * 16;
    const int o0  = blockIdx.y * 16;
    const int ff  = tid & 15;
    const int oog = (tid >> 4) & 7;       // o = o0 + oog*2 + j, j<2
    const int bbg = tid >> 7;             // b = bbg*8 + l, l<8

    ull acc[2][8];
#pragma unroll
    for (int j = 0; j < 2; j++)
#pragma unroll
        for (int l = 0; l < 8; l++) acc[j][l] = 0ull;

    for (int ic = 0; ic < 32; ic += 4) {
        __syncthreads();
        // stage X: 2048 float2 = 1024 float4, 2 per thread
#pragma unroll
        for (int q = 0; q < 2; q++) {
            int flat4 = tid + 512 * q;        // = ii*256 + rr*8 + f4
            int f4 = flat4 & 7;
            int rr = (flat4 >> 3) & 31;
            int ii = flat4 >> 8;
            int row = rr * 32 + ic + ii;      // b*32+i
            ((float4*)Xs)[flat4] = ((const float4*)(Xf + (size_t)row * FH + f0))[f4];
        }
        // stage G (o-half): 1024 float2 = 512 float4, 1 per thread
        {
            int f4 = tid & 7;
            int rr = (tid >> 3) & 15;
            int ii = tid >> 7;
            int row = (o0 + rr) * 32 + ic + ii;
            ((float4*)Gs)[tid] = ((const float4*)(Gf + (size_t)row * FH + f0))[f4];
        }
        __syncthreads();
#pragma unroll
        for (int ii = 0; ii < 4; ii++) {
            float2 ga = Gs[(ii * 16 + oog * 2 + 0) * 16 + ff];
            float2 gb = Gs[(ii * 16 + oog * 2 + 1) * 16 + ff];
            ull gp0 = pk2(ga.x, ga.y), gq0 = pk2(-ga.y, ga.x);
            ull gp1 = pk2(gb.x, gb.y), gq1 = pk2(-gb.y, gb.x);
#pragma unroll
            for (int l = 0; l < 8; l++) {
                float2 xv = Xs[(ii * 32 + bbg * 8 + l) * 16 + ff];
                ull bx = pk2(xv.x, xv.x);
                ull by = pk2(xv.y, xv.y);
                acc[0][l] = fma2(bx, gp0, acc[0][l]);
                acc[0][l] = fma2(by, gq0, acc[0][l]);
                acc[1][l] = fma2(bx, gp1, acc[1][l]);
                acc[1][l] = fma2(by, gq1, acc[1][l]);
            }
        }
    }
#pragma unroll
    for (int j = 0; j < 2; j++)
#pragma unroll
        for (int l = 0; l < 8; l++) {
            float2 v;
            upk2(v.x, v.y, acc[j][l]);
            int b = bbg * 8 + l;
            int o = o0 + oog * 2 + j;
            Of[(size_t)(b * 32 + o) * FH + f0 + ff] = v;
        }
}

// ---------------------------------------------------------------------------
extern "C" void kernel_launch(void* const* d_in, const int* in_sizes, int n_in,
                              void* d_out, int out_size) {
    const float* x       = (const float*)d_in[0];
    const float* rel_pos = (const float*)d_in[1];
    const float* w1      = (const float*)d_in[2];
    const float* b1      = (const float*)d_in[3];
    const float* omega1  = (const float*)d_in[4];
    const float* w2      = (const float*)d_in[5];
    const float* b2      = (const float*)d_in[6];
    const float* omega2  = (const float*)d_in[7];
    const float* w3      = (const float*)d_in[8];
    const float* b3      = (const float*)d_in[9];
    const float* bias    = (const float*)d_in[10];
    float* out = (float*)d_out;

    gen_kernel<<<dim3(16, 8), 256>>>(rel_pos, w1, b1, omega1, w2, b2, omega2, w3, b3);
    fft4096_kernel<false><<<1024, 256, FFT_SMEM_BYTES>>>(x, nullptr, nullptr);  // x->Xf, g->Gf
    pointwise_kernel<<<dim3(129, 2), 512>>>();                                  // Xf*Gf -> Of
    fft4096_kernel<true><<<512, 256, FFT_SMEM_BYTES>>>(nullptr, out, bias);     // Of -> out
}

// round 12
// speedup vs baseline: 1.3320x; 1.0841x over previous
#include <cuda_runtime.h>

#define BB    32
#define CINC  32
#define COUTC 32
#define TT    2048
#define DKK   32
#define NFFT  4096
#define FH    2064   // half-spectrum row stride (f = 0..2048 valid; 16-float2 aligned)

// FFT dynamic smem: 4096-pt buffer + 256-entry twiddle table
#define FFT_SMEM_BYTES ((NFFT + 256) * sizeof(float2))   // 34816

// smem bank-conflict swizzle for the FFT buffer (float2 index domain)
#define SW(i) ((i) ^ ((((i) >> 4) & 15)))

// ---- scratch (device globals; allocation-free) -----------------------------
__device__ float  g_buf[COUTC * CINC * TT];   // [o*32+i][d]   8 MB
__device__ float2 Xf[1024 * FH];              // [b*32+i][f]
__device__ float2 Gf[1024 * FH];              // [o*32+i][f]
__device__ float2 Of[1024 * FH];              // [b*32+o][f]

__device__ __forceinline__ float2 cmulf(float2 a, float2 b) {
    return make_float2(a.x * b.x - a.y * b.y, a.x * b.y + a.y * b.x);
}
__device__ __forceinline__ float2 caddf(float2 a, float2 b) { return make_float2(a.x + b.x, a.y + b.y); }
__device__ __forceinline__ float2 csubf(float2 a, float2 b) { return make_float2(a.x - b.x, a.y - b.y); }

// packed f32x2 helpers (Blackwell FFMA2)
typedef unsigned long long ull;
__device__ __forceinline__ ull pk2(float lo, float hi) {
    ull d; asm("mov.b64 %0, {%1, %2};" : "=l"(d) : "f"(lo), "f"(hi)); return d;
}
__device__ __forceinline__ void upk2(float& lo, float& hi, ull v) {
    asm("mov.b64 {%0, %1}, %2;" : "=f"(lo), "=f"(hi) : "l"(v));
}
__device__ __forceinline__ ull fma2(ull a, ull b, ull c) {
    ull d; asm("fma.rn.f32x2 %0, %1, %2, %3;" : "=l"(d) : "l"(a), "l"(b), "l"(c)); return d;
}

// ---------------------------------------------------------------------------
// 16-point DFT codelet (registers only, in place).
// ---------------------------------------------------------------------------
template<bool INV>
__device__ __forceinline__ void dft16(float2* a) {
    const float c1 = 0.92387953251128675613f;
    const float s1 = 0.38268343236508977173f;
    const float Cc = 0.70710678118654752440f;
    float2 B[16];
#pragma unroll
    for (int n0 = 0; n0 < 4; n0++) {
        float2 p0 = a[n0], p1 = a[4 + n0], p2 = a[8 + n0], p3 = a[12 + n0];
        float2 t0 = caddf(p0, p2), t1 = csubf(p0, p2);
        float2 t2 = caddf(p1, p3), t3 = csubf(p1, p3);
        float2 t3r = INV ? make_float2(-t3.y, t3.x) : make_float2(t3.y, -t3.x);
        B[n0 * 4 + 0] = caddf(t0, t2);
        B[n0 * 4 + 1] = caddf(t1, t3r);
        B[n0 * 4 + 2] = csubf(t0, t2);
        B[n0 * 4 + 3] = csubf(t1, t3r);
    }
    const float sg = INV ? 1.f : -1.f;
    const float2 w1 = make_float2(c1, sg * s1);
    const float2 w2 = make_float2(Cc, sg * Cc);
    const float2 w3 = make_float2(s1, sg * c1);
    const float2 w6 = make_float2(-Cc, sg * Cc);
    const float2 w9 = make_float2(-c1, -sg * s1);
    B[5]  = cmulf(B[5],  w1);
    B[6]  = cmulf(B[6],  w2);
    B[7]  = cmulf(B[7],  w3);
    B[9]  = cmulf(B[9],  w2);
    B[10] = INV ? make_float2(-B[10].y, B[10].x) : make_float2(B[10].y, -B[10].x);
    B[11] = cmulf(B[11], w6);
    B[13] = cmulf(B[13], w3);
    B[14] = cmulf(B[14], w6);
    B[15] = cmulf(B[15], w9);
#pragma unroll
    for (int r0 = 0; r0 < 4; r0++) {
        float2 p0 = B[r0], p1 = B[4 + r0], p2 = B[8 + r0], p3 = B[12 + r0];
        float2 t0 = caddf(p0, p2), t1 = csubf(p0, p2);
        float2 t2 = caddf(p1, p3), t3 = csubf(p1, p3);
        float2 t3r = INV ? make_float2(-t3.y, t3.x) : make_float2(t3.y, -t3.x);
        a[r0]      = caddf(t0, t2);
        a[4 + r0]  = caddf(t1, t3r);
        a[8 + r0]  = csubf(t0, t2);
        a[12 + r0] = csubf(t1, t3r);
    }
}

// ---------------------------------------------------------------------------
// SIREN MLP -> g_buf.  g[o,i,d] = kern[o,i,2048-d], d in [0,2048).
// ---------------------------------------------------------------------------
__global__ void __launch_bounds__(256)
gen_kernel(const float* __restrict__ rel_pos,
           const float* __restrict__ w1,
           const float* __restrict__ b1,
           const float* __restrict__ omega1p,
           const float* __restrict__ w2,
           const float* __restrict__ b2,
           const float* __restrict__ omega2p,
           const float* __restrict__ w3,
           const float* __restrict__ b3) {
    __shared__ float h2s[128][33];
    __shared__ float w3s[128][32];
    __shared__ float b3s[128];
    const int tid = threadIdx.x;
    const int j2b0 = blockIdx.y * 128;

#pragma unroll
    for (int q = 0; q < 4; q++) {
        int flat4 = tid + 256 * q;
        int row = flat4 >> 3;
        int c4  = flat4 & 7;
        ((float4*)&w3s[row][0])[c4] = ((const float4*)(w3 + (size_t)(j2b0 + row) * 32))[c4];
    }
    if (tid < 128) b3s[tid] = b3[j2b0 + tid];

    if (tid < 128) {
        const int kl = tid;
        const int k  = 1 + blockIdx.x * 128 + kl;
        const float pos = rel_pos[k];
        const float o1 = *omega1p, o2 = *omega2p;
        float h1[DKK];
#pragma unroll
        for (int j = 0; j < DKK; j++)
            h1[j] = sinf(o1 * (w1[j] * pos + b1[j]));
        for (int j = 0; j < DKK; j++) {
            float a = b2[j];
#pragma unroll
            for (int l = 0; l < DKK; l++)
                a += w2[j * DKK + l] * h1[l];
            h2s[kl][j] = sinf(o2 * a);
        }
    }
    __syncthreads();

    const int kl   = tid & 127;
    const int half = tid >> 7;
    const int k    = 1 + blockIdx.x * 128 + kl;
    const int d    = 2048 - k;
    float h2r[32];
#pragma unroll
    for (int l = 0; l < 32; l++) h2r[l] = h2s[kl][l];

    for (int jj = 0; jj < 64; jj++) {
        const int row = half * 64 + jj;
        float a = b3s[row];
#pragma unroll
        for (int l4 = 0; l4 < 8; l4++) {
            float4 w = ((const float4*)&w3s[row][0])[l4];
            a += w.x * h2r[4*l4+0] + w.y * h2r[4*l4+1]
               + w.z * h2r[4*l4+2] + w.w * h2r[4*l4+3];
        }
        g_buf[(size_t)(j2b0 + row) * TT + d] = a;
    }
}

// ---------------------------------------------------------------------------
// 4096-pt radix-16 Stockham FFT (3 stages), packed-real, one pair per block.
// 256 threads, 16 elements each (R8 version: chained twiddles, direct
// global loads in stage 0, direct stores for the inverse).
// FWD (INV=false): gsel=0 -> x rows -> Xf ; gsel=1 -> g rows -> Gf
// INV: full spectrum of O1 + i*O2 rebuilt in the register load; out = re/im.
// ---------------------------------------------------------------------------
template<bool INV>
__global__ void __launch_bounds__(256, 4)
fft4096_kernel(const float* __restrict__ rsrc,
               float* __restrict__ rdst,
               const float* __restrict__ bias,
               int gsel) {
    extern __shared__ float2 dyn[];
    float2* buf = dyn;                 // NFFT (swizzled indexing)
    float2* tws = dyn + NFFT;          // 256
    const int tid = threadIdx.x;

    const int sig = blockIdx.x;               // pair index in [0,512)
    const int isG = INV ? 0 : gsel;
    const int hb  = sig >> 4;
    const int ip  = sig & 15;
    const int rowA = hb * 32 + 2 * ip;

    // twiddle table exp(-2πi t/4096); own entry also used as stage-0 twiddle
    float sv, cv;
    sincospif(-(float)tid / 2048.0f, &sv, &cv);
    tws[tid] = make_float2(cv, sv);

    // ---- stage 0: registers straight from global --------------------------
    float2 a[16];
    if (!INV) {
        const float* baseA = isG ? (g_buf + (size_t)rowA * TT)
                                 : (rsrc + (size_t)rowA * TT);
        const float* baseB = baseA + TT;
#pragma unroll
        for (int r = 0; r < 8; r++) {
            int idx = tid + 256 * r;
            a[r] = make_float2(baseA[idx], baseB[idx]);
        }
#pragma unroll
        for (int r = 8; r < 16; r++) a[r] = make_float2(0.f, 0.f);   // folded
    } else {
        const float2* srcA = Of + (size_t)rowA * FH;
        const float2* srcB = srcA + FH;
#pragma unroll
        for (int r = 0; r < 16; r++) {
            int f = tid + 256 * r;
            if (f <= 2048) {
                float2 o1 = srcA[f], o2 = srcB[f];
                a[r] = make_float2(o1.x - o2.y, o1.y + o2.x);
            } else {
                int fp = NFFT - f;               // 1..2047, reversed-coalesced
                float2 o1 = srcA[fp], o2 = srcB[fp];
                a[r] = make_float2(o1.x + o2.y, o2.x - o1.y);
            }
        }
    }
    dft16<INV>(a);
    {   // jm = tid, k = 0, m = 1 -> own twiddle, no table dependency
        float2 W1 = make_float2(cv, INV ? -sv : sv);
        const int wb = 16 * tid;
        buf[SW(wb)] = a[0];
        float2 Wc = W1;
#pragma unroll
        for (int r = 1; r < 16; r++) {
            buf[SW(wb + r)] = cmulf(a[r], Wc);
            Wc = cmulf(Wc, W1);
        }
    }
    __syncthreads();

    // ---- stage 1: smem -> smem (m = 16) ------------------------------------
    {
#pragma unroll
        for (int r = 0; r < 16; r++) a[r] = buf[SW(tid + 256 * r)];
        __syncthreads();
        dft16<INV>(a);
        const int k  = tid & 15;
        const int jm = tid - k;
        const int wb = 16 * jm + k;
        float2 W1 = tws[jm];
        if (INV) W1.y = -W1.y;
        buf[SW(wb)] = a[0];
        float2 Wc = W1;
#pragma unroll
        for (int r = 1; r < 16; r++) {
            buf[SW(wb + 16 * r)] = cmulf(a[r], Wc);
            Wc = cmulf(Wc, W1);
        }
        __syncthreads();
    }

    // ---- stage 2: smem -> registers (m = 256; jm = 0, no twiddles) --------
#pragma unroll
    for (int r = 0; r < 16; r++) a[r] = buf[SW(tid + 256 * r)];
    dft16<INV>(a);
    // output index of a[r] is exactly tid + 256*r

    if (!INV) {
        // need cross-thread mirror for unpack: one smem round
        __syncthreads();
#pragma unroll
        for (int r = 0; r < 16; r++) buf[SW(tid + 256 * r)] = a[r];
        __syncthreads();
        float2* dstA = (isG ? Gf : Xf) + (size_t)rowA * FH;
        float2* dstB = dstA + FH;
#pragma unroll
        for (int q = 0; q < 8; q++) {
            int f  = tid + 256 * q;              // 0..2047
            int fm = (NFFT - f) & (NFFT - 1);
            float2 z  = buf[SW(f)];
            float2 zm = buf[SW(fm)];
            dstA[f] = make_float2(0.5f * (z.x + zm.x), 0.5f * (z.y - zm.y));
            dstB[f] = make_float2(0.5f * (z.y + zm.y), 0.5f * (zm.x - z.x));
        }
        if (tid == 0) {
            float2 z = buf[SW(2048)];
            dstA[2048] = make_float2(z.x, 0.f);
            dstB[2048] = make_float2(z.y, 0.f);
        }
    } else {
        // direct register -> global store
        const float sc = 1.0f / (float)NFFT;
        const float bv1 = bias[(rowA) & 31];
        const float bv2 = bias[(rowA + 1) & 31];
        float* dst1 = rdst + (size_t)rowA * TT;
        float* dst2 = dst1 + TT;
#pragma unroll
        for (int r = 0; r < 8; r++) {
            int t = tid + 256 * r;
            dst1[t] = a[r].x * sc + bv1;
            dst2[t] = a[r].y * sc + bv2;
        }
    }
}

// ---------------------------------------------------------------------------
// Pointwise per-frequency complex GEMM (one-wave register GEMM, FFMA2):
//   Of[b,o,f] = sum_i Xf[b,i,f] * Gf[o,i,f]   (R8 version, best measured)
// grid (129), 512 threads; block = all 32 b x 32 o for a 16-wide f tile.
// ---------------------------------------------------------------------------
__global__ void __launch_bounds__(512)
pointwise_kernel() {
    __shared__ float2 Xs[4 * 32 * 16];   // [ii][b][ff] 16 KB
    __shared__ float2 Gs[4 * 32 * 16];   // [ii][o][ff] 16 KB
    const int tid = threadIdx.x;
    const int f0  = blockIdx.x * 16;
    const int ff  = tid & 15;
    const int oo0 = ((tid >> 4) & 7) * 4;
    const int bb0 = (tid >> 7) * 8;

    ull acc[4][8];
#pragma unroll
    for (int j = 0; j < 4; j++)
#pragma unroll
        for (int l = 0; l < 8; l++) acc[j][l] = 0ull;

    for (int ic = 0; ic < 32; ic += 4) {
        __syncthreads();
#pragma unroll
        for (int q = 0; q < 2; q++) {
            int flat4 = tid + 512 * q;        // = ii*256 + rr*8 + f4
            int f4 = flat4 & 7;
            int rr = (flat4 >> 3) & 31;
            int ii = flat4 >> 8;
            int row = rr * 32 + ic + ii;      // b*32+i  (== o*32+i)
            ((float4*)Xs)[flat4] = ((const float4*)(Xf + (size_t)row * FH + f0))[f4];
            ((float4*)Gs)[flat4] = ((const float4*)(Gf + (size_t)row * FH + f0))[f4];
        }
        __syncthreads();
#pragma unroll
        for (int ii = 0; ii < 4; ii++) {
            ull gp[4], gq[4];
#pragma unroll
            for (int j = 0; j < 4; j++) {
                float2 g = Gs[(ii * 32 + oo0 + j) * 16 + ff];
                gp[j] = pk2(g.x, g.y);
                gq[j] = pk2(-g.y, g.x);
            }
#pragma unroll
            for (int l = 0; l < 8; l++) {
                float2 xv = Xs[(ii * 32 + bb0 + l) * 16 + ff];
                ull bx = pk2(xv.x, xv.x);
                ull by = pk2(xv.y, xv.y);
#pragma unroll
                for (int j = 0; j < 4; j++) {
                    acc[j][l] = fma2(bx, gp[j], acc[j][l]);
                    acc[j][l] = fma2(by, gq[j], acc[j][l]);
                }
            }
        }
    }
#pragma unroll
    for (int j = 0; j < 4; j++)
#pragma unroll
        for (int l = 0; l < 8; l++) {
            float2 v;
            upk2(v.x, v.y, acc[j][l]);
            Of[(size_t)((bb0 + l) * 32 + oo0 + j) * FH + f0 + ff] = v;
        }
}

// ---------------------------------------------------------------------------
// Forked-capture launch graph:
//   main:  xFFT ─────────────┐
//   s2:    gen → gFFT ───────┴→ pointwise → invFFT
// ---------------------------------------------------------------------------
extern "C" void kernel_launch(void* const* d_in, const int* in_sizes, int n_in,
                              void* d_out, int out_size) {
    const float* x       = (const float*)d_in[0];
    const float* rel_pos = (const float*)d_in[1];
    const float* w1      = (const float*)d_in[2];
    const float* b1      = (const float*)d_in[3];
    const float* omega1  = (const float*)d_in[4];
    const float* w2      = (const float*)d_in[5];
    const float* b2      = (const float*)d_in[6];
    const float* omega2  = (const float*)d_in[7];
    const float* w3      = (const float*)d_in[8];
    const float* b3      = (const float*)d_in[9];
    const float* bias    = (const float*)d_in[10];
    float* out = (float*)d_out;

    static cudaStream_t s2 = nullptr;
    static cudaEvent_t eFork = nullptr, eJoin = nullptr;
    if (s2 == nullptr) {   // created on the (non-captured) correctness call
        cudaStreamCreateWithFlags(&s2, cudaStreamNonBlocking);
        cudaEventCreateWithFlags(&eFork, cudaEventDisableTiming);
        cudaEventCreateWithFlags(&eJoin, cudaEventDisableTiming);
    }

    // fork: s2 branches off the main (capturing) stream
    cudaEventRecord(eFork, 0);
    cudaStreamWaitEvent(s2, eFork, 0);

    // side branch: gen -> g-FFT
    gen_kernel<<<dim3(16, 8), 256, 0, s2>>>(rel_pos, w1, b1, omega1, w2, b2, omega2, w3, b3);
    fft4096_kernel<false><<<512, 256, FFT_SMEM_BYTES, s2>>>(nullptr, nullptr, nullptr, 1); // g->Gf

    // main branch: x-FFT (independent of gen)
    fft4096_kernel<false><<<512, 256, FFT_SMEM_BYTES>>>(x, nullptr, nullptr, 0);           // x->Xf

    // join: main waits for the side branch
    cudaEventRecord(eJoin, s2);
    cudaStreamWaitEvent(0, eJoin, 0);

    pointwise_kernel<<<129, 512>>>();                                                      // Xf*Gf -> Of
    fft4096_kernel<true><<<512, 256, FFT_SMEM_BYTES>>>(nullptr, out, bias, 0);             // Of -> out
}